// round 15
// baseline (speedup 1.0000x reference)
#include <cuda_runtime.h>

// LocallyConnectedLinear: out[b,h,w,o] = sum_k xpatch[b,h,w,k] * W[h,w,k,o]
// x:  [8, 32, 32, 64]  f32 (NHWC)   W: [30, 30, 576, 64] f32 (k = c*9+kh*3+kw)
// out:[8, 30, 30, 64]  f32
//
// R11 29.4us (best): 256-bit weight loads + evict_last residency (700 locs).
// R14: RESIDENT 760 overflowed the evict_last pool (warm-only regression).
// Key model fix: scalar FFMA rt_SMSP=2 -> pure fma-pipe floor ~15us; the warm
//   (L2-resident) steady state is ~50% FMA-ISSUE-bound, not memory-bound.
// R15: FFMA2 paired over adjacent CHANNELS: weight pair = free u64 half of
//   the LDG.256; x staged duplicated (v,v) in smem (36.9KB, reduction
//   aliases inside). 16 FFMA2/iter instead of 32 FFMA, zero extra ALU ops.
//   fma floor 15 -> 7.5us. RESIDENT back to 700.

#define H_OUT 30
#define W_OUT 30
#define H_IN  32
#define W_IN  32
#define C_IN  64
#define C_OUT 64
#define KK    576   // 64 * 3 * 3
#define BATCH 8
#define NTHREADS 128
#define NSLICE 8
#define KPS    72   // KK / NSLICE
#define RESIDENT_LOCS 700   // 103.2 MB tagged evict_last (pool cap ~105MB)

typedef unsigned long long u64;

struct W8 { u64 a, b, c, d; };   // 8 floats = 4 channel-pairs = 32 bytes

__device__ __forceinline__ W8 ldg256_keep(const void* p) {
    W8 v;
    asm("ld.global.L2::evict_last.v4.b64 {%0,%1,%2,%3}, [%4];"
        : "=l"(v.a), "=l"(v.b), "=l"(v.c), "=l"(v.d) : "l"(p));
    return v;
}
__device__ __forceinline__ W8 ldg256_stream(const void* p) {
    W8 v;
    asm("ld.global.L2::evict_first.v4.b64 {%0,%1,%2,%3}, [%4];"
        : "=l"(v.a), "=l"(v.b), "=l"(v.c), "=l"(v.d) : "l"(p));
    return v;
}
__device__ __forceinline__ u64 fma2(u64 a, u64 b, u64 c) {
    u64 d;
    asm("fma.rn.f32x2 %0, %1, %2, %3;" : "=l"(d) : "l"(a), "l"(b), "l"(c));
    return d;
}
__device__ __forceinline__ u64 add2(u64 a, u64 b) {
    u64 d;
    asm("add.rn.f32x2 %0, %1, %2;" : "=l"(d) : "l"(a), "l"(b));
    return d;
}
// acc[j] (j=0..3, channel pair) += (x,x) * w-pair j
__device__ __forceinline__ void fma2x4(u64* acc, u64 xdup, const W8& w) {
    acc[0] = fma2(xdup, w.a, acc[0]);
    acc[1] = fma2(xdup, w.b, acc[1]);
    acc[2] = fma2(xdup, w.c, acc[2]);
    acc[3] = fma2(xdup, w.d, acc[3]);
}

__global__ __launch_bounds__(NTHREADS, 6)
void lc_kernel(const float* __restrict__ x,
               const float* __restrict__ w,
               float* __restrict__ out)
{
    // Phase 1: xdup[k][b] = (v,v) u64, KK*8 = 36864 B.
    // Phase 2 (aliased): red[8][16][9] float4 = 18432 B (fits inside).
    __shared__ __align__(16) u64 xdup[KK * BATCH];

    const int loc = blockIdx.x;          // 0..899
    const int h   = loc / W_OUT;
    const int wo  = loc - h * W_OUT;
    const int tid = threadIdx.x;

    // ---- Stage im2col patch duplicated: xdup[k*8+b] = (v,v);
    //      k = c*9 + kh*3 + kw (c fastest in idx -> coalesced x reads) ----
    #pragma unroll
    for (int idx = tid; idx < BATCH * KK; idx += NTHREADS) {
        const int b   = idx / KK;
        const int r   = idx - b * KK;     // (kh*3+kw)*64 + c
        const int khw = r >> 6;
        const int c   = r & 63;
        const int kh  = khw / 3;
        const int kw  = khw - kh * 3;
        const int k   = c * 9 + khw;
        const float v = x[(((b * H_IN) + h + kh) * W_IN + (wo + kw)) * C_IN + c];
        const float2 d2 = make_float2(v, v);
        xdup[k * BATCH + b] = *(const u64*)&d2;
    }
    __syncthreads();

    // ---- Main loop: thread = (ks, bh, o8); 256-bit weight loads.
    // Warp = 2 ks x 2 bh x 8 o8. x LDS: 4 distinct addrs at k*64+bh*32
    // (offsets 0/32/64/96 mod 128) -> conflict-free broadcast.
    const int o8 = tid & 7;           // 8-channel group (channels o8*8..+7)
    const int bh = (tid >> 3) & 1;    // batch half: b = bh*4 .. bh*4+3
    const int ks = tid >> 4;          // 0..7 k slice (blocked, 72 rows)
    const char* __restrict__ Wp =
        (const char*)(w + (size_t)loc * (KK * C_OUT)) + o8 * 32;

    u64 acc[4][4];    // [batch 0..3 within half][channel pair 0..3] = 32 regs
    #pragma unroll
    for (int b = 0; b < 4; ++b)
        #pragma unroll
        for (int j = 0; j < 4; ++j) acc[b][j] = 0ull;

    const int kbeg = ks * KPS;
    if (loc < RESIDENT_LOCS) {
        #pragma unroll 4
        for (int k = kbeg; k < kbeg + KPS; ++k) {
            const W8 wv = ldg256_keep(Wp + (size_t)k * 256);
            const u64* xp = &xdup[k * BATCH + bh * 4];   // 4 dup'd batches
            const ulonglong2 x01 = *(const ulonglong2*)(xp);
            const ulonglong2 x23 = *(const ulonglong2*)(xp + 2);
            fma2x4(acc[0], x01.x, wv);
            fma2x4(acc[1], x01.y, wv);
            fma2x4(acc[2], x23.x, wv);
            fma2x4(acc[3], x23.y, wv);
        }
    } else {
        #pragma unroll 4
        for (int k = kbeg; k < kbeg + KPS; ++k) {
            const W8 wv = ldg256_stream(Wp + (size_t)k * 256);
            const u64* xp = &xdup[k * BATCH + bh * 4];
            const ulonglong2 x01 = *(const ulonglong2*)(xp);
            const ulonglong2 x23 = *(const ulonglong2*)(xp + 2);
            fma2x4(acc[0], x01.x, wv);
            fma2x4(acc[1], x01.y, wv);
            fma2x4(acc[2], x23.x, wv);
            fma2x4(acc[3], x23.y, wv);
        }
    }

    // ---- Reduce 8 k-slices through smem (aliased; R11 layout) ----
    __syncthreads();   // everyone done reading xdup
    float4* red = (float4*)xdup;   // [NSLICE][16 g][9 b-pad] = 1152 float4
    #pragma unroll
    for (int b = 0; b < 4; ++b) {
        const int gb = bh * 4 + b;
        #pragma unroll
        for (int m = 0; m < 2; ++m) {
            const int g = o8 * 2 + m;     // global float4 group 0..15
            const ulonglong2 pr = make_ulonglong2(acc[b][2 * m], acc[b][2 * m + 1]);
            red[(ks * 16 + g) * 9 + gb] = *(const float4*)&pr;
        }
    }
    __syncthreads();

    {
        const int g = tid & 15;   // float4 group
        const int b = tid >> 4;   // 0..7
        ulonglong2 s = *(const ulonglong2*)&red[g * 9 + b];
        #pragma unroll
        for (int sl = 1; sl < NSLICE; ++sl) {
            const ulonglong2 p = *(const ulonglong2*)&red[(sl * 16 + g) * 9 + b];
            s.x = add2(s.x, p.x);
            s.y = add2(s.y, p.y);
        }
        ulonglong2* __restrict__ op =
            (ulonglong2*)(out + ((((size_t)b * H_OUT) + h) * W_OUT + wo) * C_OUT);
        op[g] = s;
    }
}

extern "C" void kernel_launch(void* const* d_in, const int* in_sizes, int n_in,
                              void* d_out, int out_size)
{
    const float* x  = (const float*)d_in[0];   // [8,32,32,64]
    const float* w  = (const float*)d_in[1];   // [30,30,576,64]
    float*       o  = (float*)d_out;           // [8,30,30,64]
    (void)in_sizes; (void)n_in; (void)out_size;

    lc_kernel<<<H_OUT * W_OUT, NTHREADS>>>(x, w, o);
}

// round 16
// speedup vs baseline: 1.1860x; 1.1860x over previous
#include <cuda_runtime.h>

// LocallyConnectedLinear: out[b,h,w,o] = sum_k xpatch[b,h,w,k] * W[h,w,k,o]
// x:  [8, 32, 32, 64]  f32 (NHWC)   W: [30, 30, 576, 64] f32 (k = c*9+kh*3+kw)
// out:[8, 30, 30, 64]  f32
//
// R11 29.4us (best): 256-bit weight loads + evict_last residency (700 locs).
// R15: FFMA2 failed a 3rd time (intrinsic: f32x2 pairs don't double fma
//   throughput here). Retired. Warm state is L2-latency/MLP-bound.
// R16 = R11 + occupancy/MLP push, memory pattern untouched:
//   __launch_bounds__(128,7) (28 warps/SM, regs<=72) + unroll 8
//   (~8 LDG.256 in flight/warp). Outstanding bytes/SM up ~2.3x.

#define H_OUT 30
#define W_OUT 30
#define H_IN  32
#define W_IN  32
#define C_IN  64
#define C_OUT 64
#define KK    576   // 64 * 3 * 3
#define BATCH 8
#define NTHREADS 128
#define NSLICE 8
#define KPS    72   // KK / NSLICE
#define RESIDENT_LOCS 700   // 103.2 MB tagged evict_last (pool cap ~105MB)

typedef unsigned long long u64;

struct W8 { u64 a, b, c, d; };   // 8 floats = 32 bytes

__device__ __forceinline__ W8 ldg256_keep(const void* p) {
    W8 v;
    asm("ld.global.L2::evict_last.v4.b64 {%0,%1,%2,%3}, [%4];"
        : "=l"(v.a), "=l"(v.b), "=l"(v.c), "=l"(v.d) : "l"(p));
    return v;
}
__device__ __forceinline__ W8 ldg256_stream(const void* p) {
    W8 v;
    asm("ld.global.L2::evict_first.v4.b64 {%0,%1,%2,%3}, [%4];"
        : "=l"(v.a), "=l"(v.b), "=l"(v.c), "=l"(v.d) : "l"(p));
    return v;
}
__device__ __forceinline__ void fma8(float* acc, float s, const W8& w) {
    const float* wf = (const float*)&w;
    #pragma unroll
    for (int i = 0; i < 8; ++i) acc[i] += s * wf[i];
}

__global__ __launch_bounds__(NTHREADS, 7)
void lc_kernel(const float* __restrict__ x,
               const float* __restrict__ w,
               float* __restrict__ out)
{
    // Phase 1: xs[k][b], 18 KB. Phase 2 (aliased): red[8][16][9] float4 18 KB.
    __shared__ __align__(16) float smem[KK * BATCH];

    const int loc = blockIdx.x;          // 0..899
    const int h   = loc / W_OUT;
    const int wo  = loc - h * W_OUT;
    const int tid = threadIdx.x;

    // ---- Stage im2col patch: xs[k][b], k = c*9 + kh*3 + kw (c fastest) ----
    #pragma unroll
    for (int idx = tid; idx < BATCH * KK; idx += NTHREADS) {
        const int b   = idx / KK;
        const int r   = idx - b * KK;     // (kh*3+kw)*64 + c
        const int khw = r >> 6;
        const int c   = r & 63;
        const int kh  = khw / 3;
        const int kw  = khw - kh * 3;
        const int k   = c * 9 + khw;
        smem[k * BATCH + b] =
            x[(((b * H_IN) + h + kh) * W_IN + (wo + kw)) * C_IN + c];
    }
    __syncthreads();

    // ---- Main loop: thread = (ks, bh, o8). 256-bit weight loads.
    // Warp = 2 ks x 2 bh x 8 o8: 8 o8 lanes cover one full 256B k-row;
    // bh duplicates coalesce away. Each weight byte read exactly once.
    const int o8 = tid & 7;           // 8-channel group (channels o8*8..+7)
    const int bh = (tid >> 3) & 1;    // batch half: b = bh*4 .. bh*4+3
    const int ks = tid >> 4;          // 0..7 k slice (blocked, 72 rows)
    const char* __restrict__ Wp =
        (const char*)(w + (size_t)loc * (KK * C_OUT)) + o8 * 32;

    float acc[4][8];                  // 4 batches x 8 channels = 32 regs
    #pragma unroll
    for (int b = 0; b < 4; ++b)
        #pragma unroll
        for (int i = 0; i < 8; ++i) acc[b][i] = 0.f;

    const int kbeg = ks * KPS;
    if (loc < RESIDENT_LOCS) {
        #pragma unroll 8
        for (int k = kbeg; k < kbeg + KPS; ++k) {
            const W8 wv = ldg256_keep(Wp + (size_t)k * 256);
            const float4 xq = *(const float4*)&smem[k * BATCH + bh * 4];
            fma8(acc[0], xq.x, wv);
            fma8(acc[1], xq.y, wv);
            fma8(acc[2], xq.z, wv);
            fma8(acc[3], xq.w, wv);
        }
    } else {
        #pragma unroll 8
        for (int k = kbeg; k < kbeg + KPS; ++k) {
            const W8 wv = ldg256_stream(Wp + (size_t)k * 256);
            const float4 xq = *(const float4*)&smem[k * BATCH + bh * 4];
            fma8(acc[0], xq.x, wv);
            fma8(acc[1], xq.y, wv);
            fma8(acc[2], xq.z, wv);
            fma8(acc[3], xq.w, wv);
        }
    }

    // ---- Reduce 8 k-slices through smem (aliased; R11 layout) ----
    __syncthreads();   // everyone done reading xs
    float4* red = (float4*)smem;   // [NSLICE][16 g][9 b-pad] = 1152 float4
    #pragma unroll
    for (int b = 0; b < 4; ++b) {
        const int gb = bh * 4 + b;
        #pragma unroll
        for (int j = 0; j < 2; ++j) {
            const int g = o8 * 2 + j;     // global float4 group 0..15
            red[(ks * 16 + g) * 9 + gb] = *(const float4*)&acc[b][j * 4];
        }
    }
    __syncthreads();

    {
        const int g = tid & 15;   // float4 group
        const int b = tid >> 4;   // 0..7
        float4 s = red[g * 9 + b];
        #pragma unroll
        for (int sl = 1; sl < NSLICE; ++sl) {
            const float4 p = red[(sl * 16 + g) * 9 + b];
            s.x += p.x; s.y += p.y; s.z += p.z; s.w += p.w;
        }
        float4* __restrict__ op =
            (float4*)(out + ((((size_t)b * H_OUT) + h) * W_OUT + wo) * C_OUT);
        op[g] = s;
    }
}

extern "C" void kernel_launch(void* const* d_in, const int* in_sizes, int n_in,
                              void* d_out, int out_size)
{
    const float* x  = (const float*)d_in[0];   // [8,32,32,64]
    const float* w  = (const float*)d_in[1];   // [30,30,576,64]
    float*       o  = (float*)d_out;           // [8,30,30,64]
    (void)in_sizes; (void)n_in; (void)out_size;

    lc_kernel<<<H_OUT * W_OUT, NTHREADS>>>(x, w, o);
}

// round 17
// speedup vs baseline: 1.2796x; 1.0789x over previous
#include <cuda_runtime.h>

// LocallyConnectedLinear: out[b,h,w,o] = sum_k xpatch[b,h,w,k] * W[h,w,k,o]
// x:  [8, 32, 32, 64]  f32 (NHWC)   W: [30, 30, 576, 64] f32 (k = c*9+kh*3+kw)
// out:[8, 30, 30, 64]  f32
//
// Final configuration after 16 rounds:
//   R11 29.4us (champion): 256-bit weight loads, each weight byte read once,
//     L2 evict_last residency for 700/900 locations (103MB; pool cap ~105MB,
//     760 overflowed in R14), evict_first for the streamed remainder.
//   Retired directions (all regressed or neutral): FFMA2 (x3), occupancy
//     pushes, o-/k-split grids, TMA pipelines, deeper unroll.
//   R17 = exact R11 + 2-deep register prefetch of the weight stream issued
//     BEFORE the staging barrier (isolated-positive component of R14).

#define H_OUT 30
#define W_OUT 30
#define H_IN  32
#define W_IN  32
#define C_IN  64
#define C_OUT 64
#define KK    576   // 64 * 3 * 3
#define BATCH 8
#define NTHREADS 128
#define NSLICE 8
#define KPS    72   // KK / NSLICE
#define RESIDENT_LOCS 700   // 103.2 MB tagged evict_last

typedef unsigned long long u64;

struct W8 { u64 a, b, c, d; };   // 8 floats = 32 bytes

__device__ __forceinline__ W8 ldg256_keep(const void* p) {
    W8 v;
    asm("ld.global.L2::evict_last.v4.b64 {%0,%1,%2,%3}, [%4];"
        : "=l"(v.a), "=l"(v.b), "=l"(v.c), "=l"(v.d) : "l"(p));
    return v;
}
__device__ __forceinline__ W8 ldg256_stream(const void* p) {
    W8 v;
    asm("ld.global.L2::evict_first.v4.b64 {%0,%1,%2,%3}, [%4];"
        : "=l"(v.a), "=l"(v.b), "=l"(v.c), "=l"(v.d) : "l"(p));
    return v;
}
__device__ __forceinline__ void fma8(float* acc, float s, const W8& w) {
    const float* wf = (const float*)&w;
    #pragma unroll
    for (int i = 0; i < 8; ++i) acc[i] += s * wf[i];
}

__global__ __launch_bounds__(NTHREADS, 6)
void lc_kernel(const float* __restrict__ x,
               const float* __restrict__ w,
               float* __restrict__ out)
{
    // Phase 1: xs[k][b], 18 KB. Phase 2 (aliased): red[8][16][9] float4 18 KB.
    __shared__ __align__(16) float smem[KK * BATCH];

    const int loc = blockIdx.x;          // 0..899
    const int h   = loc / W_OUT;
    const int wo  = loc - h * W_OUT;
    const int tid = threadIdx.x;

    // Thread mapping (computed early for the prefetch).
    const int o8 = tid & 7;           // 8-channel group (channels o8*8..+7)
    const int bh = (tid >> 3) & 1;    // batch half: b = bh*4 .. bh*4+3
    const int ks = tid >> 4;          // 0..7 k slice (blocked, 72 rows)
    const char* __restrict__ Wp =
        (const char*)(w + (size_t)loc * (KK * C_OUT)) + o8 * 32;
    const int kbeg = ks * KPS;
    const bool resident = (loc < RESIDENT_LOCS);

    // ---- Prefetch first 2 weight rows: DRAM latency hides under staging ----
    W8 p0, p1;
    if (resident) {
        p0 = ldg256_keep(Wp + (size_t)(kbeg + 0) * 256);
        p1 = ldg256_keep(Wp + (size_t)(kbeg + 1) * 256);
    } else {
        p0 = ldg256_stream(Wp + (size_t)(kbeg + 0) * 256);
        p1 = ldg256_stream(Wp + (size_t)(kbeg + 1) * 256);
    }

    // ---- Stage im2col patch: xs[k][b], k = c*9 + kh*3 + kw (c fastest) ----
    #pragma unroll
    for (int idx = tid; idx < BATCH * KK; idx += NTHREADS) {
        const int b   = idx / KK;
        const int r   = idx - b * KK;     // (kh*3+kw)*64 + c
        const int khw = r >> 6;
        const int c   = r & 63;
        const int kh  = khw / 3;
        const int kw  = khw - kh * 3;
        const int k   = c * 9 + khw;
        smem[k * BATCH + b] =
            x[(((b * H_IN) + h + kh) * W_IN + (wo + kw)) * C_IN + c];
    }
    __syncthreads();

    float acc[4][8];                  // 4 batches x 8 channels = 32 regs
    #pragma unroll
    for (int b = 0; b < 4; ++b)
        #pragma unroll
        for (int i = 0; i < 8; ++i) acc[b][i] = 0.f;

    // ---- Consume the 2 prefetched rows ----
    {
        const float4 xq0 = *(const float4*)&smem[(kbeg + 0) * BATCH + bh * 4];
        fma8(acc[0], xq0.x, p0);
        fma8(acc[1], xq0.y, p0);
        fma8(acc[2], xq0.z, p0);
        fma8(acc[3], xq0.w, p0);
        const float4 xq1 = *(const float4*)&smem[(kbeg + 1) * BATCH + bh * 4];
        fma8(acc[0], xq1.x, p1);
        fma8(acc[1], xq1.y, p1);
        fma8(acc[2], xq1.z, p1);
        fma8(acc[3], xq1.w, p1);
    }

    // ---- Main loop: 256-bit weight loads; each weight byte read once.
    // Warp = 2 ks x 2 bh x 8 o8: 8 o8 lanes cover one full 256B k-row;
    // bh duplicates coalesce away. ----
    if (resident) {
        #pragma unroll 4
        for (int k = kbeg + 2; k < kbeg + KPS; ++k) {
            const W8 wv = ldg256_keep(Wp + (size_t)k * 256);
            const float4 xq = *(const float4*)&smem[k * BATCH + bh * 4];
            fma8(acc[0], xq.x, wv);
            fma8(acc[1], xq.y, wv);
            fma8(acc[2], xq.z, wv);
            fma8(acc[3], xq.w, wv);
        }
    } else {
        #pragma unroll 4
        for (int k = kbeg + 2; k < kbeg + KPS; ++k) {
            const W8 wv = ldg256_stream(Wp + (size_t)k * 256);
            const float4 xq = *(const float4*)&smem[k * BATCH + bh * 4];
            fma8(acc[0], xq.x, wv);
            fma8(acc[1], xq.y, wv);
            fma8(acc[2], xq.z, wv);
            fma8(acc[3], xq.w, wv);
        }
    }

    // ---- Reduce 8 k-slices through smem (aliased; R11 layout) ----
    __syncthreads();   // everyone done reading xs
    float4* red = (float4*)smem;   // [NSLICE][16 g][9 b-pad] = 1152 float4
    #pragma unroll
    for (int b = 0; b < 4; ++b) {
        const int gb = bh * 4 + b;
        #pragma unroll
        for (int j = 0; j < 2; ++j) {
            const int g = o8 * 2 + j;     // global float4 group 0..15
            red[(ks * 16 + g) * 9 + gb] = *(const float4*)&acc[b][j * 4];
        }
    }
    __syncthreads();

    {
        const int g = tid & 15;   // float4 group
        const int b = tid >> 4;   // 0..7
        float4 s = red[g * 9 + b];
        #pragma unroll
        for (int sl = 1; sl < NSLICE; ++sl) {
            const float4 p = red[(sl * 16 + g) * 9 + b];
            s.x += p.x; s.y += p.y; s.z += p.z; s.w += p.w;
        }
        float4* __restrict__ op =
            (float4*)(out + ((((size_t)b * H_OUT) + h) * W_OUT + wo) * C_OUT);
        op[g] = s;
    }
}

extern "C" void kernel_launch(void* const* d_in, const int* in_sizes, int n_in,
                              void* d_out, int out_size)
{
    const float* x  = (const float*)d_in[0];   // [8,32,32,64]
    const float* w  = (const float*)d_in[1];   // [30,30,576,64]
    float*       o  = (float*)d_out;           // [8,30,30,64]
    (void)in_sizes; (void)n_in; (void)out_size;

    lc_kernel<<<H_OUT * W_OUT, NTHREADS>>>(x, w, o);
}